// round 8
// baseline (speedup 1.0000x reference)
#include <cuda_runtime.h>
#include <cuda_bf16.h>
#include <cstdint>

// ---- problem constants ----
#define HDIM 300
#define HPAD 320          // padded k extent (bf16 elems)
#define HPAIR 160         // uint32 (bf16x2) pairs per row
#define BROWS 4096
#define BM 128            // batch rows per CTA
#define BH 40             // hidden units per CTA -> 8 h-blocks
#define BNC 160           // gate-columns per CTA (4*BH)
#define KPAIR 16          // k-pairs per tile (BK=32)
#define SMS 20            // smem row stride in uint32 (16 + 4 pad) -> conflict-free
#define NKT 10            // k-tiles per GEMM segment
#define NTHREADS 256
#define NW 1280           // padded row-permuted weight rows
#define PAIRSZ (BROWS * HPAIR)
#define GRIDSZ 256        // 32 m-tiles x 8 h-blocks = one resident wave
// dynamic smem layout (uint32 units)
#define BUFU32 11520      // AsH(2560)+AsL(2560)+BsH(3200)+BsL(3200)
#define SMEM_U32 (2 * BUFU32 + 2 * BNC)

// ---- device scratch (no allocation allowed) ----
__device__ uint32_t g_zH[PAIRSZ], g_zL[PAIRSZ];
__device__ uint32_t g_h0H[2 * PAIRSZ], g_h0L[2 * PAIRSZ];   // ping-pong layer0 h
__device__ uint32_t g_oH[2 * PAIRSZ], g_oL[2 * PAIRSZ];     // ping-pong layer1 h
__device__ uint32_t g_WH[4 * NW * HPAIR], g_WL[4 * NW * HPAIR]; // Wih0,Whh0,Wih1,Whh1
__device__ float g_c0[BROWS * HDIM], g_c1[BROWS * HDIM];
__device__ unsigned g_bar_count = 0;
__device__ unsigned g_bar_gen = 0;

extern __shared__ uint32_t dynsmem[];

// ---------- helpers ----------
__device__ __forceinline__ uint32_t pack2(__nv_bfloat16 a, __nv_bfloat16 b) {
    return (uint32_t)__bfloat16_as_ushort(a) | ((uint32_t)__bfloat16_as_ushort(b) << 16);
}
__device__ __forceinline__ void split_pack(float v0, float v1, uint32_t& hi, uint32_t& lo) {
    __nv_bfloat16 h0 = __float2bfloat16(v0);
    __nv_bfloat16 h1 = __float2bfloat16(v1);
    float r0 = v0 - __bfloat162float(h0);   // exact
    float r1 = v1 - __bfloat162float(h1);
    hi = pack2(h0, h1);
    lo = pack2(__float2bfloat16(r0), __float2bfloat16(r1));
}
__device__ __forceinline__ void cp16(uint32_t* dst, const uint32_t* src) {
    unsigned sa = (unsigned)__cvta_generic_to_shared(dst);
    asm volatile("cp.async.cg.shared.global [%0], [%1], 16;" :: "r"(sa), "l"(src));
}

// Sense-reversing grid barrier (all 256 CTAs are co-resident by construction).
__device__ __forceinline__ void grid_barrier() {
    __threadfence();
    __syncthreads();
    if (threadIdx.x == 0) {
        unsigned gen = *(volatile unsigned*)&g_bar_gen;
        if (atomicAdd(&g_bar_count, 1u) == GRIDSZ - 1u) {
            g_bar_count = 0;
            __threadfence();
            atomicAdd(&g_bar_gen, 1u);
        } else {
            while (*(volatile unsigned*)&g_bar_gen == gen) __nanosleep(32);
        }
        __threadfence();
    }
    __syncthreads();
}

// ---------- prep kernels ----------
__global__ void prep_weights(const float* __restrict__ W0, const float* __restrict__ W1,
                             const float* __restrict__ W2, const float* __restrict__ W3) {
    int idx = blockIdx.x * blockDim.x + threadIdx.x;
    if (idx >= 4 * NW * HPAIR) return;
    int mat = idx / (NW * HPAIR);
    int rem = idx - mat * (NW * HPAIR);
    int n = rem / HPAIR;
    int p = rem - n * HPAIR;
    const float* W = (mat == 0) ? W0 : (mat == 1) ? W1 : (mat == 2) ? W2 : W3;
    int gate = n & 3, h = n >> 2;
    int k = p * 2;
    float v0 = 0.f, v1 = 0.f;
    if (h < HDIM) {
        const float* row = W + (size_t)(gate * HDIM + h) * HDIM;
        if (k < HDIM)     v0 = row[k];
        if (k + 1 < HDIM) v1 = row[k + 1];
    }
    uint32_t hi, lo;
    split_pack(v0, v1, hi, lo);
    g_WH[idx] = hi;
    g_WL[idx] = lo;
}

__global__ void prep_z(const float* __restrict__ z) {
    int idx = blockIdx.x * blockDim.x + threadIdx.x;
    if (idx >= PAIRSZ) return;
    int r = idx / HPAIR;
    int p = idx - r * HPAIR;
    int k = p * 2;
    float v0 = (k < HDIM) ? z[(size_t)r * HDIM + k] : 0.f;
    float v1 = (k + 1 < HDIM) ? z[(size_t)r * HDIM + k + 1] : 0.f;
    uint32_t hi, lo;
    split_pack(v0, v1, hi, lo);
    g_zH[idx] = hi;
    g_zL[idx] = lo;
}

// ---------- cell building blocks ----------
__device__ __forceinline__ void stage_tile(
    uint32_t* sbuf,
    const uint32_t* __restrict__ aH, const uint32_t* __restrict__ aL,
    const uint32_t* __restrict__ bH, const uint32_t* __restrict__ bL,
    int mBase, int nBase, int p0, int tid)
{
    uint32_t* AsH = sbuf;
    uint32_t* AsL = sbuf + 2560;
    uint32_t* BsH = sbuf + 5120;
    uint32_t* BsL = sbuf + 8320;
#pragma unroll
    for (int i = 0; i < 4; i++) {
        int s = tid + i * NTHREADS;              // 0..1023
        int r = (s >> 2) & (BM - 1);
        int q = s & 3;
        const uint32_t* src = (s < 512) ? aH : aL;
        uint32_t* dst = (s < 512) ? AsH : AsL;
        cp16(dst + r * SMS + q * 4, src + (size_t)(mBase + r) * HPAIR + p0 + q * 4);
    }
#pragma unroll
    for (int i = 0; i < 5; i++) {
        int s = tid + i * NTHREADS;              // 0..1279
        int sp = (s >= 640);
        int ss = sp ? s - 640 : s;
        int r = ss >> 2;
        int q = ss & 3;
        const uint32_t* src = sp ? bL : bH;
        uint32_t* dst = sp ? BsL : BsH;
        cp16(dst + r * SMS + q * 4, src + (size_t)(nBase + r) * HPAIR + p0 + q * 4);
    }
    asm volatile("cp.async.commit_group;");
}

#define MMA3(ACC, AH, AL, BHI, BLO)                                              \
    asm volatile("mma.sync.aligned.m16n8k16.row.col.f32.bf16.bf16.f32 "          \
        "{%0,%1,%2,%3}, {%4,%5,%6,%7}, {%8,%9}, {%0,%1,%2,%3};\n"                \
        : "+f"(ACC[0]), "+f"(ACC[1]), "+f"(ACC[2]), "+f"(ACC[3])                 \
        : "r"(AH[0]), "r"(AH[1]), "r"(AH[2]), "r"(AH[3]),                        \
          "r"(BLO[0]), "r"(BLO[1]));                                             \
    asm volatile("mma.sync.aligned.m16n8k16.row.col.f32.bf16.bf16.f32 "          \
        "{%0,%1,%2,%3}, {%4,%5,%6,%7}, {%8,%9}, {%0,%1,%2,%3};\n"                \
        : "+f"(ACC[0]), "+f"(ACC[1]), "+f"(ACC[2]), "+f"(ACC[3])                 \
        : "r"(AL[0]), "r"(AL[1]), "r"(AL[2]), "r"(AL[3]),                        \
          "r"(BHI[0]), "r"(BHI[1]));                                             \
    asm volatile("mma.sync.aligned.m16n8k16.row.col.f32.bf16.bf16.f32 "          \
        "{%0,%1,%2,%3}, {%4,%5,%6,%7}, {%8,%9}, {%0,%1,%2,%3};\n"                \
        : "+f"(ACC[0]), "+f"(ACC[1]), "+f"(ACC[2]), "+f"(ACC[3])                 \
        : "r"(AH[0]), "r"(AH[1]), "r"(AH[2]), "r"(AH[3]),                        \
          "r"(BHI[0]), "r"(BHI[1]));

__device__ __forceinline__ void mma_tile(
    const uint32_t* sbuf, float (*acc)[5][4],
    int warpM, int warpN, int gId, int tid4)
{
    const uint32_t* AsH = sbuf;
    const uint32_t* AsL = sbuf + 2560;
    const uint32_t* BsH = sbuf + 5120;
    const uint32_t* BsL = sbuf + 8320;
#pragma unroll
    for (int kk = 0; kk < 2; kk++) {
        const int ko2 = kk * 8;
        uint32_t bH[5][2], bL[5][2];
#pragma unroll
        for (int ni = 0; ni < 5; ni++) {
            int nb = warpN * 40 + ni * 8;
            bH[ni][0] = BsH[(nb + gId) * SMS + ko2 + tid4];
            bH[ni][1] = BsH[(nb + gId) * SMS + ko2 + tid4 + 4];
            bL[ni][0] = BsL[(nb + gId) * SMS + ko2 + tid4];
            bL[ni][1] = BsL[(nb + gId) * SMS + ko2 + tid4 + 4];
        }
#pragma unroll
        for (int mi = 0; mi < 4; mi++) {
            int rb = warpM * 64 + mi * 16;
            uint32_t aH[4], aL[4];
            aH[0] = AsH[(rb + gId) * SMS + ko2 + tid4];
            aH[1] = AsH[(rb + gId + 8) * SMS + ko2 + tid4];
            aH[2] = AsH[(rb + gId) * SMS + ko2 + tid4 + 4];
            aH[3] = AsH[(rb + gId + 8) * SMS + ko2 + tid4 + 4];
            aL[0] = AsL[(rb + gId) * SMS + ko2 + tid4];
            aL[1] = AsL[(rb + gId + 8) * SMS + ko2 + tid4];
            aL[2] = AsL[(rb + gId) * SMS + ko2 + tid4 + 4];
            aL[3] = AsL[(rb + gId + 8) * SMS + ko2 + tid4 + 4];
#pragma unroll
            for (int ni = 0; ni < 5; ni++) {
                MMA3(acc[mi][ni], aH, aL, bH[ni], bL[ni]);
            }
        }
    }
}

// One fused LSTM cell (bf16x2-compensated GEMMs + gate epilogue).
__device__ void run_cell(
    const uint32_t* __restrict__ xH, const uint32_t* __restrict__ xL,
    const uint32_t* __restrict__ hH, const uint32_t* __restrict__ hL,  // null at t=0
    const float* __restrict__ cprev,                                    // null at t=0
    const uint32_t* __restrict__ WxH, const uint32_t* __restrict__ WxL,
    const uint32_t* __restrict__ WhH, const uint32_t* __restrict__ WhL,
    const float* bias_s,
    uint32_t* __restrict__ hpH, uint32_t* __restrict__ hpL,             // bf16-pair h out
    float* __restrict__ houtF, int hOutStride,                          // optional fp32 h
    float* __restrict__ cout,
    int mBase, int hb)
{
    const int tid   = threadIdx.x;
    const int lane  = tid & 31;
    const int warp  = tid >> 5;
    const int warpM = warp >> 2;
    const int warpN = warp & 3;
    const int gId   = lane >> 2;
    const int tid4  = lane & 3;
    const int nBase = hb * 4;

    float acc[4][5][4];
#pragma unroll
    for (int a = 0; a < 4; a++)
#pragma unroll
        for (int b = 0; b < 5; b++)
#pragma unroll
            for (int c = 0; c < 4; c++) acc[a][b][c] = 0.f;

    const int nT = hH ? 2 * NKT : NKT;

    // prologue: stage tile 0 into buffer 0
    stage_tile(dynsmem, xH, xL, WxH, WxL, mBase, nBase, 0, tid);

#pragma unroll 1
    for (int kt = 0; kt < nT; kt++) {
        asm volatile("cp.async.wait_group 0;");
        __syncthreads();   // tile kt landed; all warps done with tile kt-1
        if (kt + 1 < nT) {
            int k2 = kt + 1;
            const uint32_t *sAH, *sAL, *sBH, *sBL;
            int p0;
            if (k2 < NKT) { sAH = xH; sAL = xL; sBH = WxH; sBL = WxL; p0 = k2 * KPAIR; }
            else          { sAH = hH; sAL = hL; sBH = WhH; sBL = WhL; p0 = (k2 - NKT) * KPAIR; }
            stage_tile(dynsmem + (size_t)(k2 & 1) * BUFU32, sAH, sAL, sBH, sBL,
                       mBase, nBase, p0, tid);
        }
        mma_tile(dynsmem + (size_t)(kt & 1) * BUFU32, acc, warpM, warpN, gId, tid4);
    }

    // epilogue: assemble i,f,g,o per hidden unit via shfl_xor(1)
    __nv_bfloat16* hpH16 = (__nv_bfloat16*)hpH;
    __nv_bfloat16* hpL16 = (__nv_bfloat16*)hpL;
#pragma unroll
    for (int mi = 0; mi < 4; mi++) {
        const int row_r = mBase + warpM * 64 + mi * 16 + gId;
#pragma unroll
        for (int ni = 0; ni < 5; ni++) {
            float c0v = acc[mi][ni][0], c1v = acc[mi][ni][1];
            float c2v = acc[mi][ni][2], c3v = acc[mi][ni][3];
            float p0 = __shfl_xor_sync(0xffffffffu, c0v, 1);
            float p1 = __shfl_xor_sync(0xffffffffu, c1v, 1);
            float p2 = __shfl_xor_sync(0xffffffffu, c2v, 1);
            float p3 = __shfl_xor_sync(0xffffffffu, c3v, 1);

            const int hl = warpN * 10 + ni * 2 + (tid4 >> 1);
            const int h = hb + hl;
            float iraw, fraw, graw, oraw;
            int row;
            if ((tid4 & 1) == 0) {
                iraw = c0v; fraw = c1v; graw = p0; oraw = p1; row = row_r;
            } else {
                iraw = p2; fraw = p3; graw = c2v; oraw = c3v; row = row_r + 8;
            }
            if (h < HDIM) {
                iraw += bias_s[4 * hl + 0];
                fraw += bias_s[4 * hl + 1];
                graw += bias_s[4 * hl + 2];
                oraw += bias_s[4 * hl + 3];
                float ig = 1.f / (1.f + expf(-iraw));
                float fg = 1.f / (1.f + expf(-fraw));
                float gg = tanhf(graw);
                float og = 1.f / (1.f + expf(-oraw));
                float cp = cprev ? cprev[(size_t)row * HDIM + h] : 0.f;
                float cn = fg * cp + ig * gg;
                float hn = og * tanhf(cn);
                cout[(size_t)row * HDIM + h] = cn;
                __nv_bfloat16 hh = __float2bfloat16(hn);
                float rem = hn - __bfloat162float(hh);
                hpH16[(size_t)row * HPAD + h] = hh;
                hpL16[(size_t)row * HPAD + h] = __float2bfloat16(rem);
                if (houtF) houtF[(size_t)row * hOutStride + h] = hn;
            }
        }
    }
}

// ---------- persistent driver kernel ----------
__global__ __launch_bounds__(NTHREADS, 2) void lstm_persistent(
    const float* __restrict__ b_ih0, const float* __restrict__ b_hh0,
    const float* __restrict__ b_ih1, const float* __restrict__ b_hh1,
    float* __restrict__ out, int T)
{
    const int bid   = blockIdx.x;
    const int mBase = (bid >> 3) * BM;   // 32 m-tiles
    const int hb    = (bid & 7) * BH;    // 8 h-blocks
    const int tid   = threadIdx.x;

    float* bias0 = (float*)(dynsmem + 2 * BUFU32);
    float* bias1 = bias0 + BNC;
    if (tid < BNC) {
        int gate = tid & 3, hl = tid >> 2, h = hb + hl;
        bias0[tid] = (h < HDIM) ? (b_ih0[gate * HDIM + h] + b_hh0[gate * HDIM + h]) : 0.f;
        bias1[tid] = (h < HDIM) ? (b_ih1[gate * HDIM + h] + b_hh1[gate * HDIM + h]) : 0.f;
    }
    __syncthreads();

    const int WSTEP = NW * HPAIR;

#pragma unroll 1
    for (int t = 0; t < T; t++) {
        const int wr = t & 1, rd = (t + 1) & 1;

        // ---- layer 0 ----
        const uint32_t* x0H = t ? g_oH + (size_t)rd * PAIRSZ : g_zH;
        const uint32_t* x0L = t ? g_oL + (size_t)rd * PAIRSZ : g_zL;
        const uint32_t* hp0H = t ? g_h0H + (size_t)rd * PAIRSZ : nullptr;
        const uint32_t* hp0L = t ? g_h0L + (size_t)rd * PAIRSZ : nullptr;
        run_cell(x0H, x0L, hp0H, hp0L, t ? g_c0 : nullptr,
                 g_WH + 0 * WSTEP, g_WL + 0 * WSTEP,
                 g_WH + 1 * WSTEP, g_WL + 1 * WSTEP,
                 bias0,
                 g_h0H + (size_t)wr * PAIRSZ, g_h0L + (size_t)wr * PAIRSZ,
                 nullptr, 0, g_c0, mBase, hb);
        grid_barrier();

        // ---- layer 1 (writes fp32 h into output slice t) ----
        const uint32_t* hp1H = t ? g_oH + (size_t)rd * PAIRSZ : nullptr;
        const uint32_t* hp1L = t ? g_oL + (size_t)rd * PAIRSZ : nullptr;
        run_cell(g_h0H + (size_t)wr * PAIRSZ, g_h0L + (size_t)wr * PAIRSZ,
                 hp1H, hp1L, t ? g_c1 : nullptr,
                 g_WH + 2 * WSTEP, g_WL + 2 * WSTEP,
                 g_WH + 3 * WSTEP, g_WL + 3 * WSTEP,
                 bias1,
                 g_oH + (size_t)wr * PAIRSZ, g_oL + (size_t)wr * PAIRSZ,
                 out + (size_t)t * HDIM, T * HDIM, g_c1, mBase, hb);
        grid_barrier();
    }
}

extern "C" void kernel_launch(void* const* d_in, const int* in_sizes, int n_in,
                              void* d_out, int out_size)
{
    const float* z     = (const float*)d_in[0];
    const float* W_ih0 = (const float*)d_in[1];
    const float* W_hh0 = (const float*)d_in[2];
    const float* b_ih0 = (const float*)d_in[3];
    const float* b_hh0 = (const float*)d_in[4];
    const float* W_ih1 = (const float*)d_in[5];
    const float* W_hh1 = (const float*)d_in[6];
    const float* b_ih1 = (const float*)d_in[7];
    const float* b_hh1 = (const float*)d_in[8];
    float* out = (float*)d_out;

    const int Bsz = in_sizes[0] / HDIM;      // 4096
    const int T   = out_size / (Bsz * HDIM); // 64
    const int WSTEP = NW * HPAIR;

    prep_weights<<<(4 * WSTEP + 255) / 256, 256>>>(W_ih0, W_hh0, W_ih1, W_hh1);
    prep_z<<<(PAIRSZ + 255) / 256, 256>>>(z);

    static int attr_done = 0;
    if (!attr_done) {
        cudaFuncSetAttribute(lstm_persistent,
                             cudaFuncAttributeMaxDynamicSharedMemorySize,
                             SMEM_U32 * 4);
        attr_done = 1;
    }
    lstm_persistent<<<GRIDSZ, NTHREADS, SMEM_U32 * 4>>>(b_ih0, b_hh0, b_ih1, b_hh1,
                                                        out, T);
}